// round 14
// baseline (speedup 1.0000x reference)
#include <cuda_runtime.h>
#include <cstdint>
#include <cmath>

#define NODES 20000
#define BATCH 8
#define DEG 32
#define NB 8
#define NPB 8                  // nodes per block (x 8 batches x 2 halves = 128 threads)
#define PITCH 33
#define PN 32                  // nodes per prep block

// RBF constants (box-independent): kq = 0.5/sigma^2 = 5.12, delta = 2.5/7.
__device__ constexpr float K2c  = 7.3865986093514926f;   // kq*log2e
__device__ constexpr float T2c  = 5.2761418638224990f;   // 2*kq*delta*log2e
__device__ constexpr float E2c  = 0.9421681899683034f;   // kq*delta^2*log2e
__device__ constexpr float OFFc = 64.0f;                 // exponent bias
__device__ constexpr float SCc  = 5.421010862427522e-20f; // 2^-64 unbias
// S2^sigma(n), sigma(n) = n(n-1)/2, S2 = 2^{-2*E2c} = 0.2708679
__device__ constexpr float S2p1  = 0.2708679f;
__device__ constexpr float S2p3  = 0.01987343f;
__device__ constexpr float S2p6  = 3.94954e-4f;
__device__ constexpr float S2p10 = 2.12620e-6f;
__device__ constexpr float S2p15 = 3.10025e-9f;
__device__ constexpr float S2p21 = 1.22446e-12f;

// Scratch (allocation-free rule: __device__ globals)
__device__ float4 g_pos_t[NODES * BATCH];   // [node][batch], pre-scaled by 2pi/box

__device__ __forceinline__ float fsin(float x) {
    float r; asm("sin.approx.ftz.f32 %0, %1;" : "=f"(r) : "f"(x)); return r;
}
__device__ __forceinline__ float fex2(float x) {
    float r; asm("ex2.approx.ftz.f32 %0, %1;" : "=f"(r) : "f"(x)); return r;
}
__device__ __forceinline__ unsigned long long pk(float a, float b) {
    unsigned long long r; asm("mov.b64 %0, {%1, %2};" : "=l"(r) : "f"(a), "f"(b)); return r;
}
__device__ __forceinline__ void upk(unsigned long long v, float& a, float& b) {
    asm("mov.b64 {%0, %1}, %2;" : "=f"(a), "=f"(b) : "l"(v));
}
__device__ __forceinline__ unsigned long long ffma2(unsigned long long a, unsigned long long b, unsigned long long c) {
    unsigned long long r; asm("fma.rn.f32x2 %0, %1, %2, %3;" : "=l"(r) : "l"(a), "l"(b), "l"(c)); return r;
}
__device__ __forceinline__ unsigned long long fmul2(unsigned long long a, unsigned long long b) {
    unsigned long long r; asm("mul.rn.f32x2 %0, %1, %2;" : "=l"(r) : "l"(a), "l"(b)); return r;
}
__device__ __forceinline__ unsigned long long fadd2(unsigned long long a, unsigned long long b) {
    unsigned long long r; asm("add.rn.f32x2 %0, %1, %2;" : "=l"(r) : "l"(a), "l"(b)); return r;
}

// Prep: smem-transpose. One 256-thread block = 32 nodes x all 8 batches.
__global__ void __launch_bounds__(256) prep_kernel(const float* __restrict__ pos,
                                                   const float* __restrict__ box) {
    __shared__ float sp[BATCH * 97];
    int t = threadIdx.x;
    int ibase = blockIdx.x * PN;
#pragma unroll
    for (int r = 0; r < 3; r++) {
        int e = t + r * 256;
        int bb = e / 96, rem = e - bb * 96;
        sp[bb * 97 + rem] = pos[((long)bb * NODES + ibase) * 3 + rem];
    }
    __syncthreads();
    const float TWOPI = 6.283185307179586f;
    float ia0 = TWOPI / box[0], ia1 = TWOPI / box[1], ia2 = TWOPI / box[2];
    int il = t >> 3, b = t & 7;
    const float* sr = sp + b * 97 + il * 3;
    g_pos_t[(ibase + il) * BATCH + b] =
        make_float4(sr[0] * ia0, sr[1] * ia1, sr[2] * ia2, 0.f);
}

// Split-basis embed: thread = (node s, batch b, half h). Half h accumulates
// bases 4h..4h+3 only -> 8 u64 accumulators (16 regs) -> higher occupancy.
// Half offset composed in the EXPONENT domain (eA + 4h*em) to avoid the
// m^4 overflow (m can reach 2^39; m^4 = inf, and 0*inf = NaN).
__global__ void __launch_bounds__(128, 8) embed_kernel(
    const float* __restrict__ box, const void* __restrict__ nbr,
    float* __restrict__ out)
{
    __shared__ int   sidx[NPB * DEG];          // 256 ints (pre-scaled by BATCH)
    __shared__ float sm[64 * PITCH];           // staging 8.4KB

    int tid = threadIdx.x;
    int h = tid & 1;           // basis half
    int b = (tid >> 1) & 7;    // batch lane
    int s = tid >> 4;          // node within block
    int ibase = blockIdx.x * NPB;
    int i = ibase + s;
    float h4 = h ? 4.0f : 0.0f;

    // nbr dtype autodetect (int64 high words zero); pre-scale by BATCH.
    {
        const int* w = (const int*)nbr;
        bool is64 = true;
#pragma unroll
        for (int k = 1; k < 16; k += 2) is64 &= (w[k] == 0);
        if (is64) {
            const long long* q = (const long long*)nbr + (long)ibase * DEG;
#pragma unroll
            for (int k = tid; k < NPB * DEG; k += 128)
                sidx[k] = (int)q[k] * BATCH;
        } else if (tid < 64) {
            int4 v = ((const int4*)(w + ibase * DEG))[tid];
            v.x *= BATCH; v.y *= BATCH; v.z *= BATCH; v.w *= BATCH;
            ((int4*)sidx)[tid] = v;
        }
    }
    __syncthreads();

    // Uniform box fold (ab into exp args + writeout scale).
    const float INV2PI = 0.15915494309189535f;
    float ab  = box[0] * INV2PI;
    float ab2 = ab * ab;
    float K2p = K2c * ab2 * ab2;
    float T2p = T2c * ab2;

    const float4* __restrict__ pt_b = g_pos_t + b;   // lane's batch column
    float4 own = pt_b[i * BATCH];

    // accumulators: 2 basis-pairs (this half) x {y, s0, s1, s2}
    unsigned long long aY[2], a0[2], a1[2], a2[2];
#pragma unroll
    for (int k = 0; k < 2; k++) { aY[k] = 0ull; a0[k] = 0ull; a1[k] = 0ull; a2[k] = 0ull; }

    const int4* srow = (const int4*)(sidx + s * DEG);
#pragma unroll 2
    for (int c4 = 0; c4 < DEG / 4; c4++) {
        int4 jj = srow[c4];                        // 1 LDS.128 per 4 edges
        int js[4] = {jj.x, jj.y, jj.z, jj.w};      // pre-scaled node*BATCH
#pragma unroll
        for (int u = 0; u < 4; u++) {
            float4 np = pt_b[js[u]];               // 16 lanes share one 128B line
            float s0 = fsin(np.x - own.x);
            float s1 = fsin(np.y - own.y);
            float s2 = fsin(np.z - own.z);
            float q  = fmaf(s0, s0, fmaf(s1, s1, s2 * s2));
            // x_n = x0 m^n S2^{sigma(n)}; this half starts at n = 4h:
            // A = 2^(eA + 4h*em) (exponent-domain compose, overflow-free),
            // B = A*m, step = m^2.
            float em = fmaf(T2p, q, -E2c);
            float eA = fmaf(-K2p * q, q, OFFc);
            float A  = fex2(fmaf(h4, em, eA));
            float m  = fex2(em);
            float mu = m * m;
            float B  = A * m;
            unsigned long long X  = pk(A, B);
            unsigned long long U  = pk(mu, mu);
            unsigned long long S0 = pk(s0, s0);
            unsigned long long S1 = pk(s1, s1);
            unsigned long long S2v = pk(s2, s2);
#pragma unroll
            for (int k = 0; k < 2; k++) {
                aY[k] = fadd2(X, aY[k]);
                a0[k] = ffma2(X, S0, a0[k]);
                a1[k] = ffma2(X, S1, a1[k]);
                a2[k] = ffma2(X, S2v, a2[k]);
                if (k < 1) X = fmul2(X, U);
            }
        }
    }

    // writeout: bases n = 4h + j, factor SC * S2^{sigma(n)} (per-half table)
    float D0 = h ? S2p6  : 1.0f;
    float D1 = h ? S2p10 : 1.0f;
    float D2 = h ? S2p15 : S2p1;
    float D3 = h ? S2p21 : S2p3;
    float vAB = ab * SCc;
    int row = tid >> 1;                            // (s,b)
#pragma unroll
    for (int k = 0; k < 2; k++) {
        float ylo, yhi, v0lo, v0hi, v1lo, v1hi, v2lo, v2hi;
        upk(aY[k], ylo, yhi);
        upk(a0[k], v0lo, v0hi);
        upk(a1[k], v1lo, v1hi);
        upk(a2[k], v2lo, v2hi);
        float Dlo = k ? D2 : D0, Dhi = k ? D3 : D1;
        float ySlo = SCc * Dlo, yShi = SCc * Dhi;
        float vSlo = vAB * Dlo, vShi = vAB * Dhi;
        int n0 = 4 * h + 2 * k, n1 = n0 + 1;
        sm[row * PITCH + n0] = ylo * ySlo;
        sm[row * PITCH + n1] = yhi * yShi;
        sm[row * PITCH + 8 + 3 * n0 + 0] = v0lo * vSlo;
        sm[row * PITCH + 8 + 3 * n0 + 1] = v1lo * vSlo;
        sm[row * PITCH + 8 + 3 * n0 + 2] = v2lo * vSlo;
        sm[row * PITCH + 8 + 3 * n1 + 0] = v0hi * vShi;
        sm[row * PITCH + 8 + 3 * n1 + 1] = v1hi * vShi;
        sm[row * PITCH + 8 + 3 * n1 + 2] = v2hi * vShi;
    }
    __syncthreads();

    // coalesced write-out, batch-major output
    // y: (B, N, 8) — 512 floats per block, 4 reps x 128 threads
#pragma unroll
    for (int r = 0; r < 4; r++) {
        int e = r * 128 + tid;                     // 0..511
        int bb = e >> 6, rem = e & 63;
        int s2 = rem >> 3, k = rem & 7;
        out[((long)bb * NODES + ibase + s2) * NB + k] = sm[(s2 * 8 + bb) * PITCH + k];
    }
    // yv: (B, N, 8, 3) after y — 192 floats per (batch, block)
    {
        float* yvo = out + (long)BATCH * NODES * NB;
#pragma unroll
        for (int bb = 0; bb < BATCH; bb++) {
#pragma unroll
            for (int rep = 0; rep < 2; rep++) {
                int f = rep * 128 + tid;           // 0..255, use 0..191
                if (f < 192) {
                    int s2 = f / 24, mcol = f - s2 * 24;
                    yvo[((long)bb * NODES + ibase) * 24 + f] =
                        sm[(s2 * 8 + bb) * PITCH + 8 + mcol];
                }
            }
        }
    }
}

extern "C" void kernel_launch(void* const* d_in, const int* in_sizes, int n_in,
                              void* d_out, int out_size)
{
    const float* pos = (const float*)d_in[0];
    const float* box = (const float*)d_in[1];
    const void*  nbr = d_in[2];
    float* out = (float*)d_out;

    prep_kernel<<<NODES / PN, 256>>>(pos, box);
    embed_kernel<<<NODES / NPB, 128>>>(box, nbr, out);
}

// round 15
// speedup vs baseline: 1.1695x; 1.1695x over previous
#include <cuda_runtime.h>
#include <cstdint>
#include <cmath>

#define NODES 20000
#define BATCH 8
#define DEG 32
#define NB 8
#define NPB 8                  // nodes per block (x 8 batches = 64 threads)
#define PITCH 33
#define PN 32                  // nodes per prep block

// RBF constants (box-independent): kq = 0.5/sigma^2 = 5.12, delta = 2.5/7.
__device__ constexpr float K2c  = 7.3865986093514926f;   // kq*log2e
__device__ constexpr float T2c  = 5.2761418638224990f;   // 2*kq*delta*log2e
__device__ constexpr float E2c  = 0.9421681899683034f;   // kq*delta^2*log2e
__device__ constexpr float OFFc = 64.0f;                 // exponent bias
__device__ constexpr float SCc  = 5.421010862427522e-20f; // 2^-64 unbias
// D_k = (S2^{k(2k-1)}, S2^{k(2k+1)}), S2 = 2^{-2*E2c} = 0.2708679
__device__ constexpr float DL1 = 0.2708679f;      // S2^1
__device__ constexpr float DH1 = 0.01987343f;     // S2^3
__device__ constexpr float DL2 = 3.94954e-4f;     // S2^6
__device__ constexpr float DH2 = 2.12620e-6f;     // S2^10
__device__ constexpr float DL3 = 3.10025e-9f;     // S2^15
__device__ constexpr float DH3 = 1.22446e-12f;    // S2^21

// Scratch (allocation-free rule: __device__ globals)
__device__ float4 g_pos_t[NODES * BATCH];   // [node][batch], pre-scaled by 2pi/box

__device__ __forceinline__ float fsin(float x) {
    float r; asm("sin.approx.ftz.f32 %0, %1;" : "=f"(r) : "f"(x)); return r;
}
__device__ __forceinline__ float fex2(float x) {
    float r; asm("ex2.approx.ftz.f32 %0, %1;" : "=f"(r) : "f"(x)); return r;
}
__device__ __forceinline__ unsigned long long pk(float a, float b) {
    unsigned long long r; asm("mov.b64 %0, {%1, %2};" : "=l"(r) : "f"(a), "f"(b)); return r;
}
__device__ __forceinline__ void upk(unsigned long long v, float& a, float& b) {
    asm("mov.b64 {%0, %1}, %2;" : "=f"(a), "=f"(b) : "l"(v));
}
__device__ __forceinline__ unsigned long long ffma2(unsigned long long a, unsigned long long b, unsigned long long c) {
    unsigned long long r; asm("fma.rn.f32x2 %0, %1, %2, %3;" : "=l"(r) : "l"(a), "l"(b), "l"(c)); return r;
}
__device__ __forceinline__ unsigned long long fmul2(unsigned long long a, unsigned long long b) {
    unsigned long long r; asm("mul.rn.f32x2 %0, %1, %2;" : "=l"(r) : "l"(a), "l"(b)); return r;
}
__device__ __forceinline__ unsigned long long fadd2(unsigned long long a, unsigned long long b) {
    unsigned long long r; asm("add.rn.f32x2 %0, %1, %2;" : "=l"(r) : "l"(a), "l"(b)); return r;
}

// Prep: smem-transpose. One 256-thread block = 32 nodes x all 8 batches.
// Coalesced 768-float read, pitch-97 conflict-free transpose, coalesced
// contiguous float4 write. pos pre-scaled by 2pi/box.
__global__ void __launch_bounds__(256) prep_kernel(const float* __restrict__ pos,
                                                   const float* __restrict__ box) {
    __shared__ float sp[BATCH * 97];
    int t = threadIdx.x;
    int ibase = blockIdx.x * PN;
#pragma unroll
    for (int r = 0; r < 3; r++) {
        int e = t + r * 256;
        int bb = e / 96, rem = e - bb * 96;
        sp[bb * 97 + rem] = pos[((long)bb * NODES + ibase) * 3 + rem];
    }
    __syncthreads();
    const float TWOPI = 6.283185307179586f;
    float ia0 = TWOPI / box[0], ia1 = TWOPI / box[1], ia2 = TWOPI / box[2];
    int il = t >> 3, b = t & 7;
    const float* sr = sp + b * 97 + il * 3;
    g_pos_t[(ibase + il) * BATCH + b] =
        make_float4(sr[0] * ia0, sr[1] * ia1, sr[2] * ia2, 0.f);
}

__global__ void __launch_bounds__(64, 12) embed_kernel(
    const float* __restrict__ box, const void* __restrict__ nbr,
    float* __restrict__ out)
{
    __shared__ int   sidx[NPB * DEG];          // 256 ints (pre-scaled by BATCH)
    __shared__ float sm[64 * PITCH];           // staging 8.4KB

    int tid = threadIdx.x;
    int b = tid & 7;           // batch lane
    int s = tid >> 3;          // node within block
    int ibase = blockIdx.x * NPB;
    int i = ibase + s;

    // nbr dtype autodetect: int64 (JAX x64) has zero high words for these
    // small non-negative indices. 8 probes -> false-detect prob 20000^-8.
    // Indices stored PRE-SCALED by BATCH.
    {
        const int* w = (const int*)nbr;
        bool is64 = true;
#pragma unroll
        for (int k = 1; k < 16; k += 2) is64 &= (w[k] == 0);
        if (is64) {
            const long long* q = (const long long*)nbr + (long)ibase * DEG;
#pragma unroll
            for (int k = tid; k < NPB * DEG; k += 64)
                sidx[k] = (int)q[k] * BATCH;
        } else {
            int4 v = ((const int4*)(w + ibase * DEG))[tid];
            v.x *= BATCH; v.y *= BATCH; v.z *= BATCH; v.w *= BATCH;
            ((int4*)sidx)[tid] = v;
        }
    }
    __syncthreads();

    // Uniform (cubic) box fold: accumulate raw sines; ab folded into the exp
    // args (K2' = K2*ab^4, T2' = T2*ab^2) and the final writeout scale.
    const float INV2PI = 0.15915494309189535f;
    float ab  = box[0] * INV2PI;
    float ab2 = ab * ab;
    float K2p = K2c * ab2 * ab2;
    float T2p = T2c * ab2;

    const float4* __restrict__ pt_b = g_pos_t + b;   // lane's batch column
    float4 own = pt_b[i * BATCH];

    // accumulators in Z-basis: Z_k = X_0 * M2^k (constant S2 powers folded
    // into the writeout via D_k): 4 basis-pairs x {y, s0, s1, s2}
    unsigned long long aY[4], a0[4], a1[4], a2[4];
#pragma unroll
    for (int k = 0; k < 4; k++) { aY[k] = 0ull; a0[k] = 0ull; a1[k] = 0ull; a2[k] = 0ull; }

    const int4* srow = (const int4*)(sidx + s * DEG);
#pragma unroll 2
    for (int c4 = 0; c4 < DEG / 4; c4++) {
        int4 jj = srow[c4];                        // 1 LDS.128 per 4 edges
        int js[4] = {jj.x, jj.y, jj.z, jj.w};      // pre-scaled node*BATCH
#pragma unroll
        for (int u = 0; u < 4; u++) {
            float4 np = pt_b[js[u]];               // 8 lanes -> one 128B line
            float s0 = fsin(np.x - own.x);
            float s1 = fsin(np.y - own.y);
            float s2 = fsin(np.z - own.z);
            float q  = fmaf(s0, s0, fmaf(s1, s1, s2 * s2));   // r = ab^2 * q
            // x_n = x0 * m^n * S2^{n(n-1)/2}; accumulate Z_k = (x0,x0*m)*M2^k,
            // S2 powers applied at writeout. x0 = 2^(OFF - K2' q^2),
            // m = 2^(T2' q - E2).
            float x0 = fex2(fmaf(-K2p * q, q, OFFc));
            float m  = fex2(fmaf(T2p, q, -E2c));
            float m2 = m * m;
            float x1 = x0 * m;
            unsigned long long X  = pk(x0, x1);
            unsigned long long M2 = pk(m2, m2);
            unsigned long long S0 = pk(s0, s0);
            unsigned long long S1 = pk(s1, s1);
            unsigned long long S2v = pk(s2, s2);
#pragma unroll
            for (int k = 0; k < 4; k++) {
                aY[k] = fadd2(X, aY[k]);
                a0[k] = ffma2(X, S0, a0[k]);
                a1[k] = ffma2(X, S1, a1[k]);
                a2[k] = ffma2(X, S2v, a2[k]);
                if (k < 3) X = fmul2(X, M2);
            }
        }
    }

    // writeout scales: unbias (SC), edge scale (ab), and folded D_k pairs
    float vSC = ab * SCc;
    const float YL[4] = {SCc, SCc * DL1, SCc * DL2, SCc * DL3};
    const float YH[4] = {SCc, SCc * DH1, SCc * DH2, SCc * DH3};
    const float VL[4] = {vSC, vSC * DL1, vSC * DL2, vSC * DL3};
    const float VH[4] = {vSC, vSC * DH1, vSC * DH2, vSC * DH3};

    // stage: row tid = (s,b); cols 0..7 = y[n], 8..31 = yv[n*3+d]
#pragma unroll
    for (int k = 0; k < 4; k++) {
        float ylo, yhi, v0lo, v0hi, v1lo, v1hi, v2lo, v2hi;
        upk(aY[k], ylo, yhi);
        upk(a0[k], v0lo, v0hi);
        upk(a1[k], v1lo, v1hi);
        upk(a2[k], v2lo, v2hi);
        int n0 = 2 * k, n1 = 2 * k + 1;
        sm[tid * PITCH + n0] = ylo * YL[k];
        sm[tid * PITCH + n1] = yhi * YH[k];
        sm[tid * PITCH + 8 + 3 * n0 + 0] = v0lo * VL[k];
        sm[tid * PITCH + 8 + 3 * n0 + 1] = v1lo * VL[k];
        sm[tid * PITCH + 8 + 3 * n0 + 2] = v2lo * VL[k];
        sm[tid * PITCH + 8 + 3 * n1 + 0] = v0hi * VH[k];
        sm[tid * PITCH + 8 + 3 * n1 + 1] = v1hi * VH[k];
        sm[tid * PITCH + 8 + 3 * n1 + 2] = v2hi * VH[k];
    }
    __syncthreads();

    // coalesced write-out, batch-major output
    // y: (B, N, 8) — 64 floats per (batch, block): exactly one per thread
    {
        int s2 = tid >> 3, k = tid & 7;
#pragma unroll
        for (int bb = 0; bb < BATCH; bb++) {
            float v = sm[(s2 * 8 + bb) * PITCH + k];
            out[((long)bb * NODES + ibase + s2) * NB + k] = v;
        }
    }
    // yv: (B, N, 8, 3) after y — 192 floats per (batch, block): 3 reps
    {
        float* yvo = out + (long)BATCH * NODES * NB;
#pragma unroll
        for (int bb = 0; bb < BATCH; bb++) {
#pragma unroll
            for (int rep = 0; rep < 3; rep++) {
                int f = rep * 64 + tid;            // 0..191 within this chunk
                int s2 = f / 24, mcol = f - s2 * 24;
                float v = sm[(s2 * 8 + bb) * PITCH + 8 + mcol];
                yvo[((long)bb * NODES + ibase) * 24 + f] = v;
            }
        }
    }
}

extern "C" void kernel_launch(void* const* d_in, const int* in_sizes, int n_in,
                              void* d_out, int out_size)
{
    const float* pos = (const float*)d_in[0];
    const float* box = (const float*)d_in[1];
    const void*  nbr = d_in[2];
    float* out = (float*)d_out;

    prep_kernel<<<NODES / PN, 256>>>(pos, box);
    embed_kernel<<<NODES / NPB, 64>>>(box, nbr, out);
}